// round 16
// baseline (speedup 1.0000x reference)
#include <cuda_runtime.h>
#include <cuda_fp16.h>
#include <math.h>
#include <math_constants.h>
#include <stdint.h>

#define B_    2
#define L_    2048
#define D_    2048
#define H_    16
#define KVH_  4
#define HD_   128
#define QKVD_ 3072
#define EPS_  1e-6f

typedef __half h16;

// ---------------------------------------------------------------------------
// Static scratch (all fp16)
// ---------------------------------------------------------------------------
__device__ h16 g_x16 [B_*L_*D_];
__device__ h16 g_wqkv[QKVD_*D_];        // rows 0-2047 Wq, 2048-2559 Wk, 2560-3071 Wv
__device__ h16 g_wo16[D_*D_];
__device__ h16 g_qkv [B_*L_*QKVD_];
__device__ h16 g_vt  [B_*KVH_*HD_*L_];
__device__ h16 g_ao  [B_*L_*D_];

// ---------------------------------------------------------------------------
// PTX helpers
// ---------------------------------------------------------------------------
__device__ __forceinline__ void mma_f16(float* c, const uint32_t* a, const uint32_t* b) {
    asm volatile(
        "mma.sync.aligned.m16n8k16.row.col.f32.f16.f16.f32 "
        "{%0,%1,%2,%3}, {%4,%5,%6,%7}, {%8,%9}, {%0,%1,%2,%3};\n"
        : "+f"(c[0]), "+f"(c[1]), "+f"(c[2]), "+f"(c[3])
        : "r"(a[0]), "r"(a[1]), "r"(a[2]), "r"(a[3]), "r"(b[0]), "r"(b[1]));
}

__device__ __forceinline__ void ldsm4(uint32_t* r, uint32_t saddr) {
    asm volatile("ldmatrix.sync.aligned.m8n8.x4.shared.b16 {%0,%1,%2,%3}, [%4];"
        : "=r"(r[0]), "=r"(r[1]), "=r"(r[2]), "=r"(r[3]) : "r"(saddr));
}

__device__ __forceinline__ void cp16(const h16* dst_s, const h16* src_g) {
    uint32_t d = (uint32_t)__cvta_generic_to_shared(dst_s);
    asm volatile("cp.async.cg.shared.global [%0], [%1], 16;\n"
                 :: "r"(d), "l"(src_g) : "memory");
}
__device__ __forceinline__ void cp_commit() {
    asm volatile("cp.async.commit_group;\n" ::: "memory");
}
template<int N>
__device__ __forceinline__ void cp_wait() {
    asm volatile("cp.async.wait_group %0;\n" :: "n"(N) : "memory");
}

__device__ __forceinline__ uint32_t cvt2(float lo, float hi) {
    uint32_t r;
    asm("cvt.rn.f16x2.f32 %0, %1, %2;" : "=r"(r) : "f"(hi), "f"(lo));
    return r;
}

// ---------------------------------------------------------------------------
// GEMM: BK=64, ldmatrix fragments, fused epilogues. (unchanged from round 15)
// MODE 0: fp32 out (O projection).
// MODE 3: merged QKV epilogue (Q/K rms+rope; V transposed store).
// ---------------------------------------------------------------------------
#define BM 128
#define BN 128
#define BK 64
#define APAD 72

#define SM_A_HALVES (2*BM*APAD)
#define SM_B_HALVES (2*BN*APAD)
#define SMEM_TB_BYTES ((SM_A_HALVES + SM_B_HALVES)*2)   // 73728

#define INVF_C 0.2076205059304601f    // log2(10000)/64

template<int MODE>
__global__ __launch_bounds__(256, 2)
void k_gemm(const h16* __restrict__ A, int lda,
            const h16* __restrict__ Bh, int ldb,
            void* __restrict__ Cv, int ldc, int K,
            const float* __restrict__ qgamma,
            const float* __restrict__ kgamma,
            h16* __restrict__ vt)
{
    extern __shared__ h16 sh[];
    h16* sA = sh;
    h16* sB = sh + SM_A_HALVES;

    const int tid = threadIdx.x;
    const int m0 = blockIdx.y * BM;
    const int n0 = blockIdx.x * BN;

    const h16* Ap = A  + (size_t)m0 * lda;
    const h16* Bp = Bh + (size_t)n0 * ldb;

    const int lane = tid & 31;
    const int g    = lane >> 2;
    const int t    = lane & 3;
    const int warp = tid >> 5;
    const int wm   = warp >> 2;
    const int wn   = warp & 3;

    const int a_row = (lane & 7) + ((lane >> 3) & 1) * 8;
    const int a_c8  = ((lane >> 4) & 1) * 8;
    const int b_row = (lane & 7) + ((lane >> 4) & 1) * 8;
    const int b_c8  = ((lane >> 3) & 1) * 8;

    const uint32_t sAu = (uint32_t)__cvta_generic_to_shared(sA);
    const uint32_t sBu = (uint32_t)__cvta_generic_to_shared(sB);

    float acc[4][4][4];
#pragma unroll
    for (int i = 0; i < 4; i++)
#pragma unroll
        for (int j = 0; j < 4; j++)
#pragma unroll
            for (int c = 0; c < 4; c++) acc[i][j][c] = 0.f;

    auto load_stage = [&](int s, int k0) {
#pragma unroll
        for (int i = 0; i < 4; i++) {
            int c   = tid + i * 256;
            int row = c >> 3, kc = c & 7;
            cp16(sA + (size_t)s*BM*APAD + row*APAD + kc*8,
                 Ap + (size_t)row * lda + k0 + kc*8);
        }
#pragma unroll
        for (int i = 0; i < 4; i++) {
            int c   = tid + i * 256;
            int row = c >> 3, kc = c & 7;
            cp16(sB + (size_t)s*BN*APAD + row*APAD + kc*8,
                 Bp + (size_t)row * ldb + k0 + kc*8);
        }
    };

    const int nk = K / BK;
    load_stage(0, 0);
    cp_commit();

    for (int ks = 0; ks < nk; ks++) {
        const int buf = ks & 1;
        if (ks + 1 < nk) {
            load_stage(buf ^ 1, (ks + 1) * BK);
            cp_commit();
            cp_wait<1>();
        } else {
            cp_wait<0>();
        }
        __syncthreads();

        const uint32_t aBase = sAu + (uint32_t)(buf*BM*APAD + (wm*64 + a_row)*APAD + a_c8) * 2u;
        const uint32_t bBase = sBu + (uint32_t)(buf*BN*APAD + (wn*32 + b_row)*APAD + b_c8) * 2u;

#pragma unroll
        for (int kk = 0; kk < 4; kk++) {
            const int ko = kk * 16;

            uint32_t ah[4][4];
#pragma unroll
            for (int mt = 0; mt < 4; mt++)
                ldsm4(ah[mt], aBase + (uint32_t)(mt*16*APAD + ko) * 2u);

            uint32_t bb[2][4];
#pragma unroll
            for (int nt2 = 0; nt2 < 2; nt2++)
                ldsm4(bb[nt2], bBase + (uint32_t)(nt2*16*APAD + ko) * 2u);

#pragma unroll
            for (int mt = 0; mt < 4; mt++)
#pragma unroll
                for (int nt2 = 0; nt2 < 2; nt2++) {
                    mma_f16(acc[mt][2*nt2],   ah[mt], bb[nt2]);
                    mma_f16(acc[mt][2*nt2+1], ah[mt], bb[nt2] + 2);
                }
        }
        __syncthreads();
    }

    // ---------------- epilogue ----------------
    if constexpr (MODE == 0) {
        float* C = (float*)Cv;
#pragma unroll
        for (int mt = 0; mt < 4; mt++) {
            const int r = m0 + wm*64 + mt*16 + g;
#pragma unroll
            for (int nt = 0; nt < 4; nt++) {
                const int c = n0 + wn*32 + nt*8 + 2*t;
                *reinterpret_cast<float2*>(&C[(size_t)r     * ldc + c]) =
                    make_float2(acc[mt][nt][0], acc[mt][nt][1]);
                *reinterpret_cast<float2*>(&C[(size_t)(r+8) * ldc + c]) =
                    make_float2(acc[mt][nt][2], acc[mt][nt][3]);
            }
        }
    } else {
        h16* C = (h16*)Cv;
        if (n0 >= 2560) {
            const int kvh = (n0 - 2560) >> 7;
#pragma unroll
            for (int mt = 0; mt < 4; mt++)
#pragma unroll
                for (int hh = 0; hh < 2; hh++) {
                    const int r  = m0 + wm*64 + mt*16 + g + hh*8;
                    const int bb2 = r >> 11;
                    const int ll = r & (L_ - 1);
#pragma unroll
                    for (int nt = 0; nt < 4; nt++) {
                        const int d = wn*32 + nt*8 + 2*t;
                        size_t base = ((size_t)(bb2*KVH_ + kvh)*HD_ + d)*L_ + ll;
                        vt[base]      = __float2half_rn(acc[mt][nt][2*hh]);
                        vt[base + L_] = __float2half_rn(acc[mt][nt][2*hh+1]);
                    }
                }
        } else {
            const float* gamma = (n0 < 2048) ? qgamma : kgamma;
            float* red = (float*)sh;
            float part[4][2];
#pragma unroll
            for (int mt = 0; mt < 4; mt++)
#pragma unroll
                for (int hh = 0; hh < 2; hh++) {
                    float p = 0.f;
#pragma unroll
                    for (int nt = 0; nt < 4; nt++) {
                        float a0 = acc[mt][nt][2*hh], a1 = acc[mt][nt][2*hh+1];
                        p += a0*a0 + a1*a1;
                    }
                    p += __shfl_xor_sync(0xffffffffu, p, 1);
                    p += __shfl_xor_sync(0xffffffffu, p, 2);
                    part[mt][hh] = p;
                }
            if (t == 0) {
#pragma unroll
                for (int mt = 0; mt < 4; mt++)
#pragma unroll
                    for (int hh = 0; hh < 2; hh++)
                        red[(wm*64 + mt*16 + g + hh*8)*4 + wn] = part[mt][hh];
            }
            __syncthreads();

            float invv[4][2];
#pragma unroll
            for (int mt = 0; mt < 4; mt++)
#pragma unroll
                for (int hh = 0; hh < 2; hh++) {
                    int rl = wm*64 + mt*16 + g + hh*8;
                    float s = red[rl*4] + red[rl*4+1] + red[rl*4+2] + red[rl*4+3];
                    invv[mt][hh] = rsqrtf(s * (1.0f/HD_) + EPS_);
                }

            float invf[4], g0[4], g1[4];
#pragma unroll
            for (int nt = 0; nt < 4; nt++) {
                int p = wn*16 + nt*4 + t;
                invf[nt] = exp2f(-(float)p * INVF_C);
                g0[nt] = gamma[2*p];
                g1[nt] = gamma[2*p+1];
            }

#pragma unroll
            for (int mt = 0; mt < 4; mt++)
#pragma unroll
                for (int hh = 0; hh < 2; hh++) {
                    const int r  = m0 + wm*64 + mt*16 + g + hh*8;
                    const float fl = (float)(r & (L_-1));
                    const float iv = invv[mt][hh];
#pragma unroll
                    for (int nt = 0; nt < 4; nt++) {
                        float sn, cs;
                        sincosf(fl * invf[nt], &sn, &cs);
                        float re = acc[mt][nt][2*hh]   * iv * g0[nt];
                        float im = acc[mt][nt][2*hh+1] * iv * g1[nt];
                        h16* dst = C + (size_t)r * ldc + n0 + wn*32 + nt*8 + 2*t;
                        *(uint32_t*)dst = cvt2(re*cs - im*sn, re*sn + im*cs);
                    }
                }
        }
    }
}

// ---------------------------------------------------------------------------
// fp32->fp16 conversion: MLP-4 (4 independent LDG.128 in flight per thread)
// ---------------------------------------------------------------------------
__device__ __forceinline__ ushort4 cvt4(float4 v) {
    uint32_t lo = 0, hi = 0;
    asm("cvt.rn.f16x2.f32 %0, %1, %2;" : "=r"(lo) : "f"(v.y), "f"(v.x));
    asm("cvt.rn.f16x2.f32 %0, %1, %2;" : "=r"(hi) : "f"(v.w), "f"(v.z));
    ushort4 r;
    r.x = (unsigned short)(lo & 0xffff);
    r.y = (unsigned short)(lo >> 16);
    r.z = (unsigned short)(hi & 0xffff);
    r.w = (unsigned short)(hi >> 16);
    return r;
}

// n4 must be a multiple of 1024 (all our sizes are)
__global__ void k_cvt_n(const float4* __restrict__ src, ushort4* __restrict__ dst,
                        uint32_t n4)
{
    uint32_t i0 = blockIdx.x * 1024u + threadIdx.x;
    float4 v0 = src[i0];
    float4 v1 = src[i0 + 256u];
    float4 v2 = src[i0 + 512u];
    float4 v3 = src[i0 + 768u];
    dst[i0]        = cvt4(v0);
    dst[i0 + 256u] = cvt4(v1);
    dst[i0 + 512u] = cvt4(v2);
    dst[i0 + 768u] = cvt4(v3);
}

// ---------------------------------------------------------------------------
// Fused flash attention (unchanged from round 14/15).
// ---------------------------------------------------------------------------
#define QPAD 136
#define VPAD2 40

#define QPL   (64*QPAD)
#define KPL2  (32*QPAD)
#define VPL2  (128*VPAD2)
#define QS_OFF 0
#define KS_OFF QPL
#define VS_OFF (KS_OFF + 2*KPL2)
#define MS_OFF_H (VS_OFF + 2*VPL2)
#define FA_SMEM_BYTES (MS_OFF_H*2 + 2*32*4)   // 55552

__global__ __launch_bounds__(128, 3)
void k_flash(const h16* __restrict__ qkv,
             const h16* __restrict__ vt,
             const int* __restrict__ mask,
             h16* __restrict__ ao)
{
    extern __shared__ h16 sm[];
    h16*   Qs = sm + QS_OFF;
    h16*   Ks = sm + KS_OFF;
    h16*   Vs = sm + VS_OFF;
    float* Ms = (float*)(sm + MS_OFF_H);

    const int tid  = threadIdx.x;
    const int lane = tid & 31;
    const int t    = lane & 3;
    const int w    = tid >> 5;

    const int qt = blockIdx.x, h = blockIdx.y, b = blockIdx.z;
    const int kvh = h >> 2;
    const int q0  = qt * 64;

    const h16* Qg = qkv + ((size_t)(b*L_ + q0)) * QKVD_ + h * HD_;
    const h16* Kg = qkv + ((size_t)(b*L_)) * QKVD_ + 2048 + kvh * HD_;
    const h16* Vg = vt + ((size_t)(b*KVH_ + kvh)) * HD_ * L_;

    const int a_row = (lane & 7) + ((lane >> 3) & 1) * 8;
    const int a_c8  = ((lane >> 4) & 1) * 8;
    const int b_row = (lane & 7) + ((lane >> 4) & 1) * 8;
    const int b_c8  = ((lane >> 3) & 1) * 8;

    const uint32_t qsu = (uint32_t)__cvta_generic_to_shared(Qs);
    const uint32_t ksu = (uint32_t)__cvta_generic_to_shared(Ks);
    const uint32_t vsu = (uint32_t)__cvta_generic_to_shared(Vs);

    const uint32_t aBase  = qsu + (uint32_t)((w*16 + a_row)*QPAD + a_c8) * 2u;
    const uint32_t kBase0 = ksu + (uint32_t)(b_row*QPAD + b_c8) * 2u;
    const uint32_t vBase0 = vsu + (uint32_t)(b_row*VPAD2 + b_c8) * 2u;

#pragma unroll
    for (int i = 0; i < 8; i++) {
        int c = tid + i * 128;
        int row = c >> 4, ch = c & 15;
        cp16(Qs + row*QPAD + ch*8, Qg + (size_t)row * QKVD_ + ch*8);
    }

    auto load_stage = [&](int s, int kt) {
        const int j0 = kt * 32;
#pragma unroll
        for (int i = 0; i < 4; i++) {
            int c = tid + i * 128;
            int row = c >> 4, ch = c & 15;
            cp16(Ks + s*KPL2 + row*QPAD + ch*8,
                 Kg + (size_t)(j0 + row) * QKVD_ + ch*8);
        }
#pragma unroll
        for (int i = 0; i < 4; i++) {
            int c = tid + i * 128;
            int row = c >> 2, ch = c & 3;
            cp16(Vs + s*VPL2 + row*VPAD2 + ch*8,
                 Vg + (size_t)row * L_ + j0 + ch*8);
        }
        if (tid < 32)
            Ms[s*32 + tid] = mask[b*L_ + j0 + tid] ? -6.0f : -1e30f;
    };

    load_stage(0, 0);
    cp_commit();
    cp_wait<0>();
    __syncthreads();

    uint32_t qf[8][4];
#pragma unroll
    for (int kk = 0; kk < 8; kk++)
        ldsm4(qf[kk], aBase + (uint32_t)(kk * 16) * 2u);

    float o[16][4];
#pragma unroll
    for (int i = 0; i < 16; i++)
#pragma unroll
        for (int c = 0; c < 4; c++) o[i][c] = 0.f;

    float lsum0 = 0.f, lsum1 = 0.f;
    const float sc = 0.08838834764831845f;

    const int NT_ = L_ / 32;
    for (int kt = 0; kt < NT_; kt++) {
        const int buf = kt & 1;
        if (kt + 1 < NT_) {
            load_stage(buf ^ 1, kt + 1);
            cp_commit();
            cp_wait<1>();
        } else {
            cp_wait<0>();
        }
        __syncthreads();

        float s[4][4];
#pragma unroll
        for (int nt = 0; nt < 4; nt++)
#pragma unroll
            for (int c = 0; c < 4; c++) s[nt][c] = 0.f;

        const uint32_t kBase = kBase0 + (uint32_t)(buf*KPL2) * 2u;

#pragma unroll
        for (int kk = 0; kk < 8; kk++) {
            const int ko = kk * 16;
            uint32_t kb0[4], kb1[4];
            ldsm4(kb0, kBase + (uint32_t)ko * 2u);
            ldsm4(kb1, kBase + (uint32_t)(16*QPAD + ko) * 2u);
            mma_f16(s[0], qf[kk], kb0);
            mma_f16(s[1], qf[kk], kb0 + 2);
            mma_f16(s[2], qf[kk], kb1);
            mma_f16(s[3], qf[kk], kb1 + 2);
        }

        const float* msf = Ms + buf*32;
        uint32_t pah[2][4];
#pragma unroll
        for (int kk = 0; kk < 2; kk++) {
            const int n0t = 2*kk, n1t = 2*kk + 1;
            float b00 = msf[8*n0t + 2*t], b01 = msf[8*n0t + 2*t + 1];
            float b10 = msf[8*n1t + 2*t], b11 = msf[8*n1t + 2*t + 1];
            float p00 = __expf(s[n0t][0]*sc + b00);
            float p01 = __expf(s[n0t][1]*sc + b01);
            float p02 = __expf(s[n0t][2]*sc + b00);
            float p03 = __expf(s[n0t][3]*sc + b01);
            float p10 = __expf(s[n1t][0]*sc + b10);
            float p11 = __expf(s[n1t][1]*sc + b11);
            float p12 = __expf(s[n1t][2]*sc + b10);
            float p13 = __expf(s[n1t][3]*sc + b11);
            lsum0 += p00 + p01 + p10 + p11;
            lsum1 += p02 + p03 + p12 + p13;
            pah[kk][0] = cvt2(p00, p01);
            pah[kk][1] = cvt2(p02, p03);
            pah[kk][2] = cvt2(p10, p11);
            pah[kk][3] = cvt2(p12, p13);
        }

        const uint32_t vBase = vBase0 + (uint32_t)(buf*VPL2) * 2u;
#pragma unroll
        for (int kk = 0; kk < 2; kk++) {
            const int ko = kk * 16;
#pragma unroll
            for (int nt2 = 0; nt2 < 8; nt2++) {
                uint32_t vb[4];
                ldsm4(vb, vBase + (uint32_t)(nt2*16*VPAD2 + ko) * 2u);
                mma_f16(o[2*nt2],   pah[kk], vb);
                mma_f16(o[2*nt2+1], pah[kk], vb + 2);
            }
        }
        __syncthreads();
    }

    lsum0 += __shfl_xor_sync(0xffffffffu, lsum0, 1);
    lsum0 += __shfl_xor_sync(0xffffffffu, lsum0, 2);
    lsum1 += __shfl_xor_sync(0xffffffffu, lsum1, 1);
    lsum1 += __shfl_xor_sync(0xffffffffu, lsum1, 2);

    const float inv0 = lsum0 > 0.f ? 1.f / lsum0 : 0.f;
    const float inv1 = lsum1 > 0.f ? 1.f / lsum1 : 0.f;
    const int g = lane >> 2;
    const int row0 = q0 + w*16 + g;
    const size_t base0 = (size_t)(b*L_ + row0) * D_ + h * HD_;
    const size_t base1 = base0 + 8 * (size_t)D_;

#pragma unroll
    for (int nt = 0; nt < 16; nt++) {
        const int col = nt*8 + 2*t;
        *(uint32_t*)(ao + base0 + col) = cvt2(o[nt][0] * inv0, o[nt][1] * inv0);
        *(uint32_t*)(ao + base1 + col) = cvt2(o[nt][2] * inv1, o[nt][3] * inv1);
    }
}

// ---------------------------------------------------------------------------
// Launch: x-cvt (default) ∥ Wq/Wk/Wv-cvt (s1) ∥ Wo-cvt (s2)
// ---------------------------------------------------------------------------
extern "C" void kernel_launch(void* const* d_in, const int* in_sizes, int n_in,
                              void* d_out, int out_size) {
    const float* x    = (const float*)d_in[0];
    const int*   mask = (const int*)  d_in[1];
    const float* Wq   = (const float*)d_in[2];
    const float* Wk   = (const float*)d_in[3];
    const float* Wv   = (const float*)d_in[4];
    const float* Wo   = (const float*)d_in[5];
    const float* qg   = (const float*)d_in[6];
    const float* kg   = (const float*)d_in[7];
    float* out = (float*)d_out;

    h16 *x16, *wqkv, *wo16, *qkvp, *vtp, *aop;
    cudaGetSymbolAddress((void**)&x16,  g_x16);
    cudaGetSymbolAddress((void**)&wqkv, g_wqkv);
    cudaGetSymbolAddress((void**)&wo16, g_wo16);
    cudaGetSymbolAddress((void**)&qkvp, g_qkv);
    cudaGetSymbolAddress((void**)&vtp,  g_vt);
    cudaGetSymbolAddress((void**)&aop,  g_ao);

    cudaFuncSetAttribute(k_flash, cudaFuncAttributeMaxDynamicSharedMemorySize,
                         FA_SMEM_BYTES);
    cudaFuncSetAttribute(k_gemm<0>, cudaFuncAttributeMaxDynamicSharedMemorySize,
                         SMEM_TB_BYTES);
    cudaFuncSetAttribute(k_gemm<3>, cudaFuncAttributeMaxDynamicSharedMemorySize,
                         SMEM_TB_BYTES);

    static cudaStream_t s1 = nullptr, s2 = nullptr;
    static cudaEvent_t e0 = nullptr, e1 = nullptr, e2 = nullptr;
    if (!s1) {
        cudaStreamCreateWithFlags(&s1, cudaStreamNonBlocking);
        cudaStreamCreateWithFlags(&s2, cudaStreamNonBlocking);
        cudaEventCreateWithFlags(&e0, cudaEventDisableTiming);
        cudaEventCreateWithFlags(&e1, cudaEventDisableTiming);
        cudaEventCreateWithFlags(&e2, cudaEventDisableTiming);
    }

    const int M = B_ * L_;
    dim3 blk(256);

    // fork point
    cudaEventRecord(e0, 0);

    // s2: Wo conversion (hidden under QKV + flash)
    cudaStreamWaitEvent(s2, e0, 0);
    k_cvt_n<<<1048576u/1024u, 256, 0, s2>>>(
        (const float4*)Wo, (ushort4*)wo16, 1048576u);
    cudaEventRecord(e2, s2);

    // s1: Wq/Wk/Wv conversions (concurrent with x conversion)
    cudaStreamWaitEvent(s1, e0, 0);
    k_cvt_n<<<1048576u/1024u, 256, 0, s1>>>(
        (const float4*)Wq, (ushort4*)wqkv, 1048576u);
    k_cvt_n<<<262144u/1024u, 256, 0, s1>>>(
        (const float4*)Wk, (ushort4*)wqkv + 1048576u, 262144u);
    k_cvt_n<<<262144u/1024u, 256, 0, s1>>>(
        (const float4*)Wv, (ushort4*)wqkv + 1310720u, 262144u);
    cudaEventRecord(e1, s1);

    // default: x conversion
    k_cvt_n<<<2097152u/1024u, 256>>>((const float4*)x, (ushort4*)x16, 2097152u);

    // join s1, merged QKV projection
    cudaStreamWaitEvent(0, e1, 0);
    k_gemm<3><<<dim3(QKVD_/BN, M/BM), blk, SMEM_TB_BYTES>>>(
        x16, D_, wqkv, D_, qkvp, QKVD_, D_, qg, kg, vtp);

    // fused flash attention
    k_flash<<<dim3(L_/64, H_, B_), 128, FA_SMEM_BYTES>>>(qkvp, vtp, mask, aop);

    // join s2, output projection (fp32 out)
    cudaStreamWaitEvent(0, e2, 0);
    k_gemm<0><<<dim3(D_/BN, M/BM), blk, SMEM_TB_BYTES>>>(
        aop, D_, wo16, D_, out, D_, D_, nullptr, nullptr, nullptr);
}